// round 15
// baseline (speedup 1.0000x reference)
#include <cuda_runtime.h>
#include <cstdint>

// DIN attention-seq-pooling, round 15: SINGLE-LAUNCH persistent kernel.
// vs round 14 (74.5us): prep_pack + prep_sort folded into the main kernel
// (blocks 0-19 pack weights, block 20 sorts by L; device-flag release/acquire
// sync; last-exiting CTA resets counters for the next graph replay). Removes
// two launches + gaps (~8us). Tile math / LPT / occupancy unchanged
// (fp16 m16n8k16, nf-outer MMA1, reg-resident h1, warp-autonomous tiles,
// 7 CTAs/SM, NCTA=1064=7x152 -> all CTAs co-resident, spin is safe).

#define TT 200
#define EE 64
#define HH1 80
#define HH2 40
#define KSTR 40      // all strides ≡ 8 mod 32 -> conflict-free LDS.64
#define B1STR 40
#define W2STR 40
#define NCTA 1064
#define MAXB 4096
#define NPREP 21     // 20 pack blocks + 1 sort block

typedef unsigned long long ull;

__device__ float  g_W1sum[EE * HH1];       // W1a + W1c, [e*80+n]
__device__ float2 g_W1pair[HH1 * EE];      // {W1b-W1c, W1d}, [n*64+e]
__device__ unsigned g_W2Th[HH2 * W2STR];   // half2 image [n][phys k2]
__device__ int    g_ctr   = 0;             // persistent work counter
__device__ int    g_ready = 0;             // prep completion flag
__device__ int    g_done  = 0;             // exit counter (self-reset)
__device__ int    g_order[MAXB];           // batch indices, descending L

// phys slot of logical half2-col c2 within its 8-col group
__host__ __device__ __forceinline__ int physcol(int c2) {
    int g = c2 >> 3, j = c2 & 7;
    return (g << 3) | ((j & 3) << 1) | (j >> 2);
}

__device__ __forceinline__ unsigned pack_h2(float lo, float hi) {
    unsigned r;
    asm("cvt.rn.f16x2.f32 %0, %1, %2;" : "=r"(r) : "f"(hi), "f"(lo));
    return r;
}
__device__ __forceinline__ float sigmoid_tanh(float x) {
    float t;
    asm("tanh.approx.f32 %0, %1;" : "=f"(t) : "f"(x * 0.5f));
    return fmaf(t, 0.5f, 0.5f);
}
__device__ __forceinline__ void mma_f16(float* d, unsigned a0, unsigned a1,
                                        unsigned a2, unsigned a3,
                                        unsigned b0, unsigned b1) {
    asm volatile(
        "mma.sync.aligned.m16n8k16.row.col.f32.f16.f16.f32 "
        "{%0,%1,%2,%3}, {%4,%5,%6,%7}, {%8,%9}, {%0,%1,%2,%3};"
        : "+f"(d[0]), "+f"(d[1]), "+f"(d[2]), "+f"(d[3])
        : "r"(a0), "r"(a1), "r"(a2), "r"(a3), "r"(b0), "r"(b1));
}

__device__ __forceinline__ bool klen_is64(const void* klen) {
    const long long* L64 = (const long long*)klen;
    return ((ull)L64[0] <= 0xFFFFFFFFull) && ((ull)L64[1] <= 0xFFFFFFFFull) &&
           ((ull)L64[2] <= 0xFFFFFFFFull) && ((ull)L64[3] <= 0xFFFFFFFFull);
}
__device__ __forceinline__ int klen_at(const void* klen, bool is64, int b) {
    int L = is64 ? (int)((const long long*)klen)[b] : ((const int*)klen)[b];
    if (L < 0) L = 0;
    if (L > TT) L = TT;
    return L;
}

// ---------------- smem layout (32-bit word index) ----------------
#define SM_K    0                         // 4 warps x 16 x 40 = 2560
#define SM_B1   2560                      // 80 x 40 = 3200 (prep: sort hist)
#define SM_W2T  5760                      // 40 x 40 = 1600
#define SM_QW   7360                      // 80 f
#define SM_B2V  7440                      // 40 f
#define SM_WD   7480                      // 40 f
#define SM_SSC  7520                      // 208 f
#define SM_PART 7728                      // 128 f
#define SM_BIDX 7856                      // 1
#define SM_WORDS 7860
#define SM_BYTES (SM_WORDS * 4)           // 31440 -> 7 CTAs/SM (regs <= 73)

__global__ void __launch_bounds__(128, 7)
din_mma_kernel(const float* __restrict__ query,
               const float* __restrict__ keys,
               const void*  __restrict__ klen,
               const float* __restrict__ W1,
               const float* __restrict__ b1,
               const float* __restrict__ W2,
               const float* __restrict__ b2,
               const float* __restrict__ Wd,
               const float* __restrict__ bd,
               float* __restrict__ out,
               int B)
{
    extern __shared__ float smf[];
    unsigned* smu = (unsigned*)smf;
    int* smi = (int*)smf;
    const int tid  = threadIdx.x;
    const int bx   = blockIdx.x;
    const int wid  = tid >> 5;
    const int lane = tid & 31;
    const int gr   = lane >> 2;     // group row 0..7
    const int tg   = lane & 3;      // thread-in-group 0..3
    const int kw   = SM_K + wid * 16 * KSTR;   // warp-private K region

    const bool is64 = klen_is64(klen);
    const bool use_order = (B <= MAXB);

    // ================= inline prep (blocks 0..NPREP-1) =================
    if (bx < 20) {
        // weight pack: W1sum, W1pair, W2Th  (cold path; spill-tolerant)
        for (int i = bx * 128 + tid; i < EE * HH1; i += 20 * 128) {
            int e = i / HH1, n = i - e * HH1;
            g_W1sum[i] = W1[i] + W1[2 * EE * HH1 + i];
            float2 p;
            p.x = W1[EE * HH1 + i] - W1[2 * EE * HH1 + i];
            p.y = W1[3 * EE * HH1 + i];
            g_W1pair[n * EE + e] = p;
        }
        for (int i = bx * 128 + tid; i < HH2 * W2STR; i += 20 * 128) {
            int n = i / W2STR, c2 = i - n * W2STR;
            g_W2Th[n * W2STR + physcol(c2)] =
                pack_h2(W2[(2 * c2) * HH2 + n], W2[(2 * c2 + 1) * HH2 + n]);
        }
        __syncthreads();
        if (tid == 0) { __threadfence(); atomicAdd(&g_ready, 1); }
    } else if (bx == 20 && use_order) {
        // counting sort of batch indices by L, descending
        int* hist = &smi[SM_B1];           // 201 ints, reused later as B1eff
        for (int i = tid; i <= TT; i += 128) hist[i] = 0;
        __syncthreads();
        for (int b2i = tid; b2i < B; b2i += 128)
            atomicAdd(&hist[klen_at(klen, is64, b2i)], 1);
        __syncthreads();
        if (tid == 0) {                    // exclusive prefix, L descending
            int acc = 0;
            for (int Lv = TT; Lv >= 0; Lv--) { int h = hist[Lv]; hist[Lv] = acc; acc += h; }
        }
        __syncthreads();
        for (int b2i = tid; b2i < B; b2i += 128) {
            int pos = atomicAdd(&hist[klen_at(klen, is64, b2i)], 1);
            g_order[pos] = b2i;
        }
        __syncthreads();
        if (tid == 0) { __threadfence(); atomicAdd(&g_ready, 1); }
    } else if (bx == 20) {
        if (tid == 0) { __threadfence(); atomicAdd(&g_ready, 1); }
    }

    // ---- acquire: wait for all prep arrivals ----
    if (tid == 0) {
        while (atomicAdd(&g_ready, 0) < NPREP) { }
    }
    __syncthreads();
    __threadfence();                        // order subsequent loads

    // ---- per-CTA one-time staging: W2T, b2, Wd ----
    if (tid < HH2) { smf[SM_B2V + tid] = b2[tid]; smf[SM_WD + tid] = Wd[tid]; }
    {
        const uint2* src = (const uint2*)g_W2Th;
        uint2* dst = (uint2*)&smu[SM_W2T];
        for (int i = tid; i < HH2 * W2STR / 2; i += 128) dst[i] = src[i];
    }
    const float bdv = bd[0];

    // ================= persistent work loop (LPT order) =================
    while (true) {
        if (tid == 0) smi[SM_BIDX] = atomicAdd(&g_ctr, 1);
        __syncthreads();               // broadcast idx; also fences prev batch
        const int idx = smi[SM_BIDX];
        if (idx >= B) break;
        const int b = use_order ? g_order[idx] : idx;

        const int L = klen_at(klen, is64, b);
        if (L == 0) {
            if (tid < EE) out[(size_t)b * EE + tid] = 0.0f;
            continue;                  // uniform; loop-top sync re-converges
        }
        const int ntiles = (L + 15) >> 4;
        const float* kb = keys + (size_t)b * TT * EE;
        const float* qb = query + (size_t)b * EE;

        // ---- prologue (one barrier): qW | B1eff ----
        if (tid < HH1) {               // qW = b1 + q @ W1sum (q via L1)
            float acc = b1[tid];
            #pragma unroll 8
            for (int e = 0; e < EE; e++)
                acc += __ldg(qb + e) * g_W1sum[e * HH1 + tid];
            smf[SM_QW + tid] = acc;
        }
        for (int i = tid; i < HH1 * (EE / 2); i += 128) {  // B1eff image
            int n = i >> 5, e2 = i & 31;
            float4 w = *(const float4*)&g_W1pair[n * EE + 2 * e2]; // {bc0,d0,bc1,d1}
            float2 q2 = __ldg((const float2*)(qb + 2 * e2));
            smu[SM_B1 + n * B1STR + physcol(e2)] = pack_h2(fmaf(q2.x, w.y, w.x),
                                                           fmaf(q2.y, w.w, w.z));
        }
        __syncthreads();

        // ---- warp-autonomous tiles: stage own K, compute, no block sync ----
        for (int mt = wid; mt < ntiles; mt += 4) {
            const int rbase = mt * 16;

            __syncwarp();              // prior tile's fragment reads done
            #pragma unroll
            for (int it = 0; it < 8; it++) {
                int idx2 = it * 32 + lane;
                int r = idx2 >> 4, c4 = idx2 & 15;
                int rg = rbase + r;
                float4 v = make_float4(0.f, 0.f, 0.f, 0.f);
                if (rg < TT) v = *(const float4*)(kb + (size_t)rg * EE + c4 * 4);
                smu[kw + r * KSTR + physcol(2 * c4)]     = pack_h2(v.x, v.y);
                smu[kw + r * KSTR + physcol(2 * c4 + 1)] = pack_h2(v.z, v.w);
            }
            __syncwarp();

            // A-fragments from private K
            uint2 af[4][2];
            #pragma unroll
            for (int ks = 0; ks < 4; ks++) {
                af[ks][0] = *(const uint2*)&smu[kw + gr * KSTR + 8 * ks + 2 * tg];
                af[ks][1] = *(const uint2*)&smu[kw + (gr + 8) * KSTR + 8 * ks + 2 * tg];
            }

            // MMA1 nf-outer; convert each d1[nf] to h1 immediately
            unsigned haA[10], haB[10];
            #pragma unroll
            for (int nf = 0; nf < 10; nf++) {
                float d1[4] = {0.f, 0.f, 0.f, 0.f};
                #pragma unroll
                for (int ks = 0; ks < 4; ks++) {
                    uint2 bf = *(const uint2*)&smu[SM_B1 + (8 * nf + gr) * B1STR
                                                   + 8 * ks + 2 * tg];
                    mma_f16(d1, af[ks][0].x, af[ks][1].x,
                                af[ks][0].y, af[ks][1].y, bf.x, bf.y);
                }
                int j0 = nf * 8 + 2 * tg;
                float qlo = smf[SM_QW + j0], qhi = smf[SM_QW + j0 + 1];
                haA[nf] = pack_h2(sigmoid_tanh(d1[0] + qlo),
                                  sigmoid_tanh(d1[1] + qhi));
                haB[nf] = pack_h2(sigmoid_tanh(d1[2] + qlo),
                                  sigmoid_tanh(d1[3] + qhi));
            }

            // MMA2: D2[16,40] = h1 @ W2T  (5 ksteps of 16)
            float d2[5][4];
            #pragma unroll
            for (int nf = 0; nf < 5; nf++)
                d2[nf][0] = d2[nf][1] = d2[nf][2] = d2[nf][3] = 0.0f;

            #pragma unroll
            for (int ks = 0; ks < 5; ks++) {
                unsigned a0 = haA[2 * ks];
                unsigned a1 = haB[2 * ks];
                unsigned a2 = haA[2 * ks + 1];
                unsigned a3 = haB[2 * ks + 1];
                #pragma unroll
                for (int nf = 0; nf < 5; nf++) {
                    uint2 bf = *(const uint2*)&smu[SM_W2T + (8 * nf + gr) * W2STR
                                                   + 8 * ks + 2 * tg];
                    mma_f16(d2[nf], a0, a1, a2, a3, bf.x, bf.y);
                }
            }

            // score = bd + sum_j sigmoid(D2+b2)*Wd ; reduce over tg
            float slo = 0.0f, shi = 0.0f;
            #pragma unroll
            for (int nf = 0; nf < 5; nf++) {
                int j0 = nf * 8 + 2 * tg;
                float blo = smf[SM_B2V + j0], bhi = smf[SM_B2V + j0 + 1];
                float wlo = smf[SM_WD + j0],  whi = smf[SM_WD + j0 + 1];
                slo += sigmoid_tanh(d2[nf][0] + blo) * wlo
                     + sigmoid_tanh(d2[nf][1] + bhi) * whi;
                shi += sigmoid_tanh(d2[nf][2] + blo) * wlo
                     + sigmoid_tanh(d2[nf][3] + bhi) * whi;
            }
            slo += __shfl_xor_sync(0xffffffffu, slo, 1);
            slo += __shfl_xor_sync(0xffffffffu, slo, 2);
            shi += __shfl_xor_sync(0xffffffffu, shi, 1);
            shi += __shfl_xor_sync(0xffffffffu, shi, 2);
            if (tg == 0) {
                int t0 = rbase + gr, t1 = rbase + gr + 8;
                if (t0 < L) smf[SM_SSC + t0] = slo + bdv;
                if (t1 < L) smf[SM_SSC + t1] = shi + bdv;
            }
        }
        __syncthreads();               // all scores in SSC

        // ---- pooling from GLOBAL fp32 k, 4 accumulators ----
        {
            int e = tid & 63, half = tid >> 6;
            const float* kp = kb + e;
            float a0 = 0.f, a1 = 0.f, a2 = 0.f, a3 = 0.f;
            int t = half;
            for (; t + 6 < L; t += 8) {
                a0 += smf[SM_SSC + t]     * kp[(size_t)t * EE];
                a1 += smf[SM_SSC + t + 2] * kp[(size_t)(t + 2) * EE];
                a2 += smf[SM_SSC + t + 4] * kp[(size_t)(t + 4) * EE];
                a3 += smf[SM_SSC + t + 6] * kp[(size_t)(t + 6) * EE];
            }
            for (; t < L; t += 2)
                a0 += smf[SM_SSC + t] * kp[(size_t)t * EE];
            smf[SM_PART + tid] = (a0 + a1) + (a2 + a3);
        }
        __syncthreads();
        if (tid < EE)
            out[(size_t)b * EE + tid] = smf[SM_PART + tid] + smf[SM_PART + EE + tid];
        // loop-top __syncthreads protects B1/SSC/PART reuse next iteration
    }

    // ================= self-reset for next graph replay =================
    if (tid == 0) {
        __threadfence();
        int d = atomicAdd(&g_done, 1);
        if (d == (int)gridDim.x - 1) {     // last CTA resets global state
            g_ctr = 0;
            g_ready = 0;
            __threadfence();
            g_done = 0;
        }
    }
}

extern "C" void kernel_launch(void* const* d_in, const int* in_sizes, int n_in,
                              void* d_out, int out_size)
{
    const float* query = (const float*)d_in[0];
    const float* keys  = (const float*)d_in[1];
    const void*  klen  = d_in[2];
    const float* W1    = (const float*)d_in[3];
    const float* b1    = (const float*)d_in[4];
    const float* W2    = (const float*)d_in[5];
    const float* b2    = (const float*)d_in[6];
    const float* Wd    = (const float*)d_in[7];
    const float* bd    = (const float*)d_in[8];
    float* out = (float*)d_out;

    const int B = in_sizes[0] / EE;  // 4096

    static int configured = 0;
    if (!configured) {
        cudaFuncSetAttribute(din_mma_kernel,
                             cudaFuncAttributeMaxDynamicSharedMemorySize, SM_BYTES);
        configured = 1;
    }

    din_mma_kernel<<<NCTA, 128, SM_BYTES>>>(query, keys, klen, W1, b1, W2, b2,
                                            Wd, bd, out, B);
}

// round 16
// speedup vs baseline: 1.1064x; 1.1064x over previous
#include <cuda_runtime.h>
#include <cstdint>

// DIN attention-seq-pooling, round 16: revert to R14 structure + single merged
// prep launch. vs round 14 (74.5us best): prep_pack and prep_sort fused into
// ONE kernel (blocks 0-19 pack weights with coalesced W2 gather, block 20
// counting-sorts batches by L descending). Main kernel byte-identical to R14
// (fp16 m16n8k16, nf-outer MMA1, reg-resident h1, warp-autonomous tiles,
// LPT order, 7 CTAs/SM, NCTA=1064). R15's in-kernel prep gate reverted:
// graph gaps (~1us) < whole-chip spin cost.

#define TT 200
#define EE 64
#define HH1 80
#define HH2 40
#define KSTR 40      // all strides ≡ 8 mod 32 -> conflict-free LDS.64
#define B1STR 40
#define W2STR 40
#define NCTA 1064
#define MAXB 4096

typedef unsigned long long ull;

__device__ float  g_W1sum[EE * HH1];       // W1a + W1c, [e*80+n]
__device__ float2 g_W1pair[HH1 * EE];      // {W1b-W1c, W1d}, [n*64+e]
__device__ unsigned g_W2Th[HH2 * W2STR];   // half2 image [n][phys k2]
__device__ int    g_ctr;                   // persistent work counter
__device__ int    g_order[MAXB];           // batch indices, descending L

// phys slot of logical half2-col c2 within its 8-col group
__host__ __device__ __forceinline__ int physcol(int c2) {
    int g = c2 >> 3, j = c2 & 7;
    return (g << 3) | ((j & 3) << 1) | (j >> 2);
}

__device__ __forceinline__ unsigned pack_h2(float lo, float hi) {
    unsigned r;
    asm("cvt.rn.f16x2.f32 %0, %1, %2;" : "=r"(r) : "f"(hi), "f"(lo));
    return r;
}
__device__ __forceinline__ float sigmoid_tanh(float x) {
    float t;
    asm("tanh.approx.f32 %0, %1;" : "=f"(t) : "f"(x * 0.5f));
    return fmaf(t, 0.5f, 0.5f);
}
__device__ __forceinline__ void mma_f16(float* d, unsigned a0, unsigned a1,
                                        unsigned a2, unsigned a3,
                                        unsigned b0, unsigned b1) {
    asm volatile(
        "mma.sync.aligned.m16n8k16.row.col.f32.f16.f16.f32 "
        "{%0,%1,%2,%3}, {%4,%5,%6,%7}, {%8,%9}, {%0,%1,%2,%3};"
        : "+f"(d[0]), "+f"(d[1]), "+f"(d[2]), "+f"(d[3])
        : "r"(a0), "r"(a1), "r"(a2), "r"(a3), "r"(b0), "r"(b1));
}

__device__ __forceinline__ bool klen_is64(const void* klen) {
    const long long* L64 = (const long long*)klen;
    return ((ull)L64[0] <= 0xFFFFFFFFull) && ((ull)L64[1] <= 0xFFFFFFFFull) &&
           ((ull)L64[2] <= 0xFFFFFFFFull) && ((ull)L64[3] <= 0xFFFFFFFFull);
}
__device__ __forceinline__ int klen_at(const void* klen, bool is64, int b) {
    int L = is64 ? (int)((const long long*)klen)[b] : ((const int*)klen)[b];
    if (L < 0) L = 0;
    if (L > TT) L = TT;
    return L;
}

// ---------------- merged prep kernel (one launch) ----------------
// blocks 0..19: weight pack (coalesced); block 20: counting sort by L desc.
__global__ void prep_all(const float* __restrict__ W1, const float* __restrict__ W2,
                         const void* __restrict__ klen, int B)
{
    const int bx = blockIdx.x, tid = threadIdx.x;
    if (bx < 20) {
        if (bx == 0 && tid == 0) g_ctr = 0;
        int i = bx * 256 + tid;
        if (i < EE * HH1) {                // i = e*80+n, coalesced W1 reads
            int e = i / HH1, n = i - e * HH1;
            g_W1sum[i] = W1[i] + W1[2 * EE * HH1 + i];
            float2 p;
            p.x = W1[EE * HH1 + i] - W1[2 * EE * HH1 + i];
            p.y = W1[3 * EE * HH1 + i];
            g_W1pair[n * EE + e] = p;
        }
        // W2 gather, n-minor: adjacent lanes read contiguous W2 addresses
        for (int j = bx * 256 + tid; j < HH2 * W2STR; j += 20 * 256) {
            int c2 = j / HH2, n = j - c2 * HH2;
            float v0 = W2[(2 * c2) * HH2 + n];
            float v1 = W2[(2 * c2 + 1) * HH2 + n];
            g_W2Th[n * W2STR + physcol(c2)] = pack_h2(v0, v1);
        }
    } else {
        // counting sort of batch indices by L, descending (outputs are
        // batch-exclusive so within-bucket order doesn't matter)
        __shared__ int hist[TT + 1];
        if (B > MAXB) return;
        for (int i = tid; i <= TT; i += 256) hist[i] = 0;
        __syncthreads();
        const bool is64 = klen_is64(klen);
        for (int b = tid; b < B; b += 256)
            atomicAdd(&hist[klen_at(klen, is64, b)], 1);
        __syncthreads();
        if (tid == 0) {                    // exclusive prefix, L descending
            int acc = 0;
            for (int L = TT; L >= 0; L--) { int h = hist[L]; hist[L] = acc; acc += h; }
        }
        __syncthreads();
        for (int b = tid; b < B; b += 256) {
            int pos = atomicAdd(&hist[klen_at(klen, is64, b)], 1);
            g_order[pos] = b;
        }
    }
}

// ---------------- smem layout (32-bit word index) ----------------
#define SM_K    0                         // 4 warps x 16 x 40 = 2560
#define SM_B1   2560                      // 80 x 40 = 3200
#define SM_W2T  5760                      // 40 x 40 = 1600
#define SM_QW   7360                      // 80 f
#define SM_B2V  7440                      // 40 f
#define SM_WD   7480                      // 40 f
#define SM_SSC  7520                      // 208 f
#define SM_PART 7728                      // 128 f
#define SM_BIDX 7856                      // 1
#define SM_WORDS 7860
#define SM_BYTES (SM_WORDS * 4)           // 31440 -> 7 CTAs/SM (regs <= 73)

__global__ void __launch_bounds__(128, 7)
din_mma_kernel(const float* __restrict__ query,
               const float* __restrict__ keys,
               const void*  __restrict__ klen,
               const float* __restrict__ b1,
               const float* __restrict__ b2,
               const float* __restrict__ Wd,
               const float* __restrict__ bd,
               float* __restrict__ out,
               int B)
{
    extern __shared__ float smf[];
    unsigned* smu = (unsigned*)smf;
    int* smi = (int*)smf;
    const int tid  = threadIdx.x;
    const int wid  = tid >> 5;
    const int lane = tid & 31;
    const int gr   = lane >> 2;     // group row 0..7
    const int tg   = lane & 3;      // thread-in-group 0..3
    const int kw   = SM_K + wid * 16 * KSTR;   // warp-private K region

    // ---- per-CTA one-time staging: W2T, b2, Wd ----
    if (tid < HH2) { smf[SM_B2V + tid] = b2[tid]; smf[SM_WD + tid] = Wd[tid]; }
    {
        const uint2* src = (const uint2*)g_W2Th;
        uint2* dst = (uint2*)&smu[SM_W2T];
        for (int i = tid; i < HH2 * W2STR / 2; i += 128) dst[i] = src[i];
    }
    const float bdv = bd[0];
    const bool is64 = klen_is64(klen);
    const bool use_order = (B <= MAXB);

    // ---- persistent work loop (LPT order) ----
    while (true) {
        if (tid == 0) smi[SM_BIDX] = atomicAdd(&g_ctr, 1);
        __syncthreads();               // broadcast idx; also fences prev batch
        const int idx = smi[SM_BIDX];
        if (idx >= B) break;
        const int b = use_order ? g_order[idx] : idx;

        const int L = klen_at(klen, is64, b);
        if (L == 0) {
            if (tid < EE) out[(size_t)b * EE + tid] = 0.0f;
            continue;                  // uniform; loop-top sync re-converges
        }
        const int ntiles = (L + 15) >> 4;
        const float* kb = keys + (size_t)b * TT * EE;
        const float* qb = query + (size_t)b * EE;

        // ---- prologue (one barrier): qW | B1eff ----
        if (tid < HH1) {               // qW = b1 + q @ W1sum (q via L1)
            float acc = b1[tid];
            #pragma unroll 8
            for (int e = 0; e < EE; e++)
                acc += __ldg(qb + e) * g_W1sum[e * HH1 + tid];
            smf[SM_QW + tid] = acc;
        }
        for (int i = tid; i < HH1 * (EE / 2); i += 128) {  // B1eff image
            int n = i >> 5, e2 = i & 31;
            float4 w = *(const float4*)&g_W1pair[n * EE + 2 * e2]; // {bc0,d0,bc1,d1}
            float2 q2 = __ldg((const float2*)(qb + 2 * e2));
            smu[SM_B1 + n * B1STR + physcol(e2)] = pack_h2(fmaf(q2.x, w.y, w.x),
                                                           fmaf(q2.y, w.w, w.z));
        }
        __syncthreads();

        // ---- warp-autonomous tiles: stage own K, compute, no block sync ----
        for (int mt = wid; mt < ntiles; mt += 4) {
            const int rbase = mt * 16;

            __syncwarp();              // prior tile's fragment reads done
            #pragma unroll
            for (int it = 0; it < 8; it++) {
                int idx2 = it * 32 + lane;
                int r = idx2 >> 4, c4 = idx2 & 15;
                int rg = rbase + r;
                float4 v = make_float4(0.f, 0.f, 0.f, 0.f);
                if (rg < TT) v = *(const float4*)(kb + (size_t)rg * EE + c4 * 4);
                smu[kw + r * KSTR + physcol(2 * c4)]     = pack_h2(v.x, v.y);
                smu[kw + r * KSTR + physcol(2 * c4 + 1)] = pack_h2(v.z, v.w);
            }
            __syncwarp();

            // A-fragments from private K
            uint2 af[4][2];
            #pragma unroll
            for (int ks = 0; ks < 4; ks++) {
                af[ks][0] = *(const uint2*)&smu[kw + gr * KSTR + 8 * ks + 2 * tg];
                af[ks][1] = *(const uint2*)&smu[kw + (gr + 8) * KSTR + 8 * ks + 2 * tg];
            }

            // MMA1 nf-outer; convert each d1[nf] to h1 immediately
            unsigned haA[10], haB[10];
            #pragma unroll
            for (int nf = 0; nf < 10; nf++) {
                float d1[4] = {0.f, 0.f, 0.f, 0.f};
                #pragma unroll
                for (int ks = 0; ks < 4; ks++) {
                    uint2 bf = *(const uint2*)&smu[SM_B1 + (8 * nf + gr) * B1STR
                                                   + 8 * ks + 2 * tg];
                    mma_f16(d1, af[ks][0].x, af[ks][1].x,
                                af[ks][0].y, af[ks][1].y, bf.x, bf.y);
                }
                int j0 = nf * 8 + 2 * tg;
                float qlo = smf[SM_QW + j0], qhi = smf[SM_QW + j0 + 1];
                haA[nf] = pack_h2(sigmoid_tanh(d1[0] + qlo),
                                  sigmoid_tanh(d1[1] + qhi));
                haB[nf] = pack_h2(sigmoid_tanh(d1[2] + qlo),
                                  sigmoid_tanh(d1[3] + qhi));
            }

            // MMA2: D2[16,40] = h1 @ W2T  (5 ksteps of 16)
            float d2[5][4];
            #pragma unroll
            for (int nf = 0; nf < 5; nf++)
                d2[nf][0] = d2[nf][1] = d2[nf][2] = d2[nf][3] = 0.0f;

            #pragma unroll
            for (int ks = 0; ks < 5; ks++) {
                unsigned a0 = haA[2 * ks];
                unsigned a1 = haB[2 * ks];
                unsigned a2 = haA[2 * ks + 1];
                unsigned a3 = haB[2 * ks + 1];
                #pragma unroll
                for (int nf = 0; nf < 5; nf++) {
                    uint2 bf = *(const uint2*)&smu[SM_W2T + (8 * nf + gr) * W2STR
                                                   + 8 * ks + 2 * tg];
                    mma_f16(d2[nf], a0, a1, a2, a3, bf.x, bf.y);
                }
            }

            // score = bd + sum_j sigmoid(D2+b2)*Wd ; reduce over tg
            float slo = 0.0f, shi = 0.0f;
            #pragma unroll
            for (int nf = 0; nf < 5; nf++) {
                int j0 = nf * 8 + 2 * tg;
                float blo = smf[SM_B2V + j0], bhi = smf[SM_B2V + j0 + 1];
                float wlo = smf[SM_WD + j0],  whi = smf[SM_WD + j0 + 1];
                slo += sigmoid_tanh(d2[nf][0] + blo) * wlo
                     + sigmoid_tanh(d2[nf][1] + bhi) * whi;
                shi += sigmoid_tanh(d2[nf][2] + blo) * wlo
                     + sigmoid_tanh(d2[nf][3] + bhi) * whi;
            }
            slo += __shfl_xor_sync(0xffffffffu, slo, 1);
            slo += __shfl_xor_sync(0xffffffffu, slo, 2);
            shi += __shfl_xor_sync(0xffffffffu, shi, 1);
            shi += __shfl_xor_sync(0xffffffffu, shi, 2);
            if (tg == 0) {
                int t0 = rbase + gr, t1 = rbase + gr + 8;
                if (t0 < L) smf[SM_SSC + t0] = slo + bdv;
                if (t1 < L) smf[SM_SSC + t1] = shi + bdv;
            }
        }
        __syncthreads();               // all scores in SSC

        // ---- pooling from GLOBAL fp32 k, 4 accumulators ----
        {
            int e = tid & 63, half = tid >> 6;
            const float* kp = kb + e;
            float a0 = 0.f, a1 = 0.f, a2 = 0.f, a3 = 0.f;
            int t = half;
            for (; t + 6 < L; t += 8) {
                a0 += smf[SM_SSC + t]     * kp[(size_t)t * EE];
                a1 += smf[SM_SSC + t + 2] * kp[(size_t)(t + 2) * EE];
                a2 += smf[SM_SSC + t + 4] * kp[(size_t)(t + 4) * EE];
                a3 += smf[SM_SSC + t + 6] * kp[(size_t)(t + 6) * EE];
            }
            for (; t < L; t += 2)
                a0 += smf[SM_SSC + t] * kp[(size_t)t * EE];
            smf[SM_PART + tid] = (a0 + a1) + (a2 + a3);
        }
        __syncthreads();
        if (tid < EE)
            out[(size_t)b * EE + tid] = smf[SM_PART + tid] + smf[SM_PART + EE + tid];
        // loop-top __syncthreads protects B1/SSC/PART reuse next iteration
    }
}

extern "C" void kernel_launch(void* const* d_in, const int* in_sizes, int n_in,
                              void* d_out, int out_size)
{
    const float* query = (const float*)d_in[0];
    const float* keys  = (const float*)d_in[1];
    const void*  klen  = d_in[2];
    const float* W1    = (const float*)d_in[3];
    const float* b1    = (const float*)d_in[4];
    const float* W2    = (const float*)d_in[5];
    const float* b2    = (const float*)d_in[6];
    const float* Wd    = (const float*)d_in[7];
    const float* bd    = (const float*)d_in[8];
    float* out = (float*)d_out;

    const int B = in_sizes[0] / EE;  // 4096

    static int configured = 0;
    if (!configured) {
        cudaFuncSetAttribute(din_mma_kernel,
                             cudaFuncAttributeMaxDynamicSharedMemorySize, SM_BYTES);
        configured = 1;
    }

    prep_all<<<21, 256>>>(W1, W2, klen, B);
    din_mma_kernel<<<NCTA, 128, SM_BYTES>>>(query, keys, klen, b1, b2, Wd, bd,
                                            out, B);
}